// round 1
// baseline (speedup 1.0000x reference)
#include <cuda_runtime.h>
#include <cuda_bf16.h>
#include <cstddef>

#define N_LIT 200000
#define N_CLS 800000
#define NE    2400000
#define CH    64
#define NVAR  (N_LIT/2)
#define NLAY  4

// ---------------- device scratch (static, no allocation) ----------------
__device__ float g_hlA[(size_t)N_LIT * CH];
__device__ float g_hlB[(size_t)N_LIT * CH];
__device__ float g_hc [(size_t)N_CLS * CH];
__device__ float g_m  [(size_t)N_CLS * CH];
__device__ int   g_cnt_lit[N_LIT];
__device__ int   g_cnt_cls[N_CLS];
__device__ float g_inv_lit[N_LIT];
__device__ float g_inv_cls[N_CLS];

__device__ __forceinline__ float silu(float x) {
    return x / (1.0f + __expf(-x));
}

// ---------------- helpers ----------------
__global__ void zero_f4(float4* __restrict__ p, int n4) {
    int i = blockIdx.x * blockDim.x + threadIdx.x;
    if (i < n4) p[i] = make_float4(0.f, 0.f, 0.f, 0.f);
}

__global__ void count_kernel(const int* __restrict__ el, const int* __restrict__ ec,
                             int* __restrict__ cl, int* __restrict__ cc) {
    int e = blockIdx.x * blockDim.x + threadIdx.x;
    if (e < NE) {
        atomicAdd(cl + el[e], 1);
        atomicAdd(cc + ec[e], 1);
    }
}

__global__ void inv_kernel(const int* __restrict__ cnt, float* __restrict__ inv, int n) {
    int i = blockIdx.x * blockDim.x + threadIdx.x;
    if (i < n) {
        int c = cnt[i];
        inv[i] = (c > 0) ? (1.0f / (float)c) : 1.0f;
    }
}

// ---------------- encoder: h = silu(x@W1+b1)@W2+b2, F=4 ----------------
__global__ void __launch_bounds__(128) encoder_kernel(
    const float* __restrict__ xl, const float* __restrict__ xc,
    const float* __restrict__ w1, const float* __restrict__ b1,
    const float* __restrict__ w2, const float* __restrict__ b2,
    float* __restrict__ hl, float* __restrict__ hc)
{
    __shared__ float sW1[4 * CH];
    __shared__ float sb1[CH];
    __shared__ float sW2[CH * CH];
    __shared__ float sb2[CH];
    for (int t = threadIdx.x; t < 64; t += 128) ((float4*)sW1)[t] = ((const float4*)w1)[t];
    for (int t = threadIdx.x; t < CH * 16; t += 128) ((float4*)sW2)[t] = ((const float4*)w2)[t];
    if (threadIdx.x < CH) { sb1[threadIdx.x] = b1[threadIdx.x]; sb2[threadIdx.x] = b2[threadIdx.x]; }
    __syncthreads();

    int i = blockIdx.x * 128 + threadIdx.x;
    if (i >= N_LIT + N_CLS) return;
    const float* x;
    float* out;
    if (i < N_LIT) { x = xl + (size_t)i * 4;           out = hl + (size_t)i * CH; }
    else           { x = xc + (size_t)(i - N_LIT) * 4; out = hc + (size_t)(i - N_LIT) * CH; }
    float x0 = x[0], x1 = x[1], x2 = x[2], x3 = x[3];

    float acc[CH];
    #pragma unroll
    for (int j = 0; j < CH; j++) acc[j] = sb2[j];

    #pragma unroll 4
    for (int k = 0; k < CH; k++) {
        float t = sb1[k] + x0 * sW1[k] + x1 * sW1[CH + k] + x2 * sW1[2 * CH + k] + x3 * sW1[3 * CH + k];
        float s = silu(t);
        const float4* wr = (const float4*)(sW2 + k * CH);
        #pragma unroll
        for (int j = 0; j < 16; j++) {
            float4 w = wr[j];
            acc[4 * j    ] += s * w.x;
            acc[4 * j + 1] += s * w.y;
            acc[4 * j + 2] += s * w.z;
            acc[4 * j + 3] += s * w.w;
        }
    }
    #pragma unroll
    for (int j = 0; j < 16; j++) {
        float4 o = make_float4(acc[4*j], acc[4*j+1], acc[4*j+2], acc[4*j+3]);
        ((float4*)out)[j] = o;
    }
}

// ---------------- edge scatter: dst[didx[e]] += src[sidx[e]] ----------------
__global__ void scatter_kernel(const float* __restrict__ src,
                               const int* __restrict__ sidx,
                               const int* __restrict__ didx,
                               float* __restrict__ dst)
{
    int w = blockIdx.x * blockDim.x + threadIdx.x;
    int e = w >> 4;
    if (e >= NE) return;
    int c = w & 15;
    int s = __ldg(sidx + e);
    int d = __ldg(didx + e);
    float4 v = __ldg((const float4*)src + (size_t)s * 16 + c);
    float* p = dst + (size_t)d * CH + c * 4;
    asm volatile("red.global.add.v4.f32 [%0], {%1,%2,%3,%4};"
                 :: "l"(p), "f"(v.x), "f"(v.y), "f"(v.z), "f"(v.w) : "memory");
}

// ---------------- cls update: hc = silu([hc, m*inv] @ Wc + bc), in place ----------------
__global__ void __launch_bounds__(128) cls_update(
    float* __restrict__ hc, const float* __restrict__ m,
    const float* __restrict__ inv,
    const float* __restrict__ W, const float* __restrict__ b)
{
    __shared__ float sW[2 * CH * CH];  // 128x64 = 32KB
    __shared__ float sb[CH];
    for (int t = threadIdx.x; t < 2 * CH * 16; t += 128) ((float4*)sW)[t] = ((const float4*)W)[t];
    if (threadIdx.x < CH) sb[threadIdx.x] = b[threadIdx.x];
    __syncthreads();

    size_t i = (size_t)blockIdx.x * 128 + threadIdx.x;
    if (i >= N_CLS) return;
    float* row = hc + i * CH;
    const float* mrow = m + i * CH;
    float iv = inv[i];

    float acc[CH];
    #pragma unroll
    for (int j = 0; j < CH; j++) acc[j] = sb[j];

    #pragma unroll 2
    for (int k = 0; k < CH; k++) {
        float xk = row[k];
        const float4* wr = (const float4*)(sW + k * CH);
        #pragma unroll
        for (int j = 0; j < 16; j++) {
            float4 w = wr[j];
            acc[4*j  ] += xk * w.x; acc[4*j+1] += xk * w.y;
            acc[4*j+2] += xk * w.z; acc[4*j+3] += xk * w.w;
        }
    }
    #pragma unroll 2
    for (int k = 0; k < CH; k++) {
        float xk = mrow[k] * iv;
        const float4* wr = (const float4*)(sW + (CH + k) * CH);
        #pragma unroll
        for (int j = 0; j < 16; j++) {
            float4 w = wr[j];
            acc[4*j  ] += xk * w.x; acc[4*j+1] += xk * w.y;
            acc[4*j+2] += xk * w.z; acc[4*j+3] += xk * w.w;
        }
    }
    #pragma unroll
    for (int j = 0; j < 16; j++) {
        float4 o = make_float4(silu(acc[4*j]), silu(acc[4*j+1]), silu(acc[4*j+2]), silu(acc[4*j+3]));
        ((float4*)row)[j] = o;
    }
}

// ---------------- lit update: hdst = silu([hsrc, m*inv, hsrc_flip] @ Wl + bl) ----------------
__global__ void __launch_bounds__(128) lit_update(
    const float* __restrict__ hsrc, float* __restrict__ hdst,
    const float* __restrict__ m, const float* __restrict__ inv,
    const float* __restrict__ W, const float* __restrict__ b)
{
    extern __shared__ float smem[];
    float* sW = smem;                    // 192*64 = 48KB
    float* sb = smem + 3 * CH * CH;
    for (int t = threadIdx.x; t < 3 * CH * 16; t += 128) ((float4*)sW)[t] = ((const float4*)W)[t];
    if (threadIdx.x < CH) sb[threadIdx.x] = b[threadIdx.x];
    __syncthreads();

    size_t i = (size_t)blockIdx.x * 128 + threadIdx.x;
    if (i >= N_LIT) return;
    const float* self = hsrc + i * CH;
    const float* flip = hsrc + (i ^ 1) * CH;
    const float* mrow = m + i * CH;
    float iv = inv[i];

    float acc[CH];
    #pragma unroll
    for (int j = 0; j < CH; j++) acc[j] = sb[j];

    #pragma unroll 2
    for (int k = 0; k < CH; k++) {
        float xk = self[k];
        const float4* wr = (const float4*)(sW + k * CH);
        #pragma unroll
        for (int j = 0; j < 16; j++) {
            float4 w = wr[j];
            acc[4*j  ] += xk * w.x; acc[4*j+1] += xk * w.y;
            acc[4*j+2] += xk * w.z; acc[4*j+3] += xk * w.w;
        }
    }
    #pragma unroll 2
    for (int k = 0; k < CH; k++) {
        float xk = mrow[k] * iv;
        const float4* wr = (const float4*)(sW + (CH + k) * CH);
        #pragma unroll
        for (int j = 0; j < 16; j++) {
            float4 w = wr[j];
            acc[4*j  ] += xk * w.x; acc[4*j+1] += xk * w.y;
            acc[4*j+2] += xk * w.z; acc[4*j+3] += xk * w.w;
        }
    }
    #pragma unroll 2
    for (int k = 0; k < CH; k++) {
        float xk = flip[k];
        const float4* wr = (const float4*)(sW + (2 * CH + k) * CH);
        #pragma unroll
        for (int j = 0; j < 16; j++) {
            float4 w = wr[j];
            acc[4*j  ] += xk * w.x; acc[4*j+1] += xk * w.y;
            acc[4*j+2] += xk * w.z; acc[4*j+3] += xk * w.w;
        }
    }
    float* out = hdst + i * CH;
    #pragma unroll
    for (int j = 0; j < 16; j++) {
        float4 o = make_float4(silu(acc[4*j]), silu(acc[4*j+1]), silu(acc[4*j+2]), silu(acc[4*j+3]));
        ((float4*)out)[j] = o;
    }
}

// ---------------- readout: y = silu(hv@W1+b1)@W2+b2, hv = [hl[2v], hl[2v+1]] ----------------
#define W1T_STRIDE 132
__global__ void __launch_bounds__(128) readout_kernel(
    const float* __restrict__ hl,
    const float* __restrict__ w1, const float* __restrict__ b1,
    const float* __restrict__ w2, const float* __restrict__ b2,
    float* __restrict__ out)
{
    extern __shared__ float smem[];
    float* sW1T = smem;                       // [128][132] transposed, padded
    float* sb1  = smem + 128 * W1T_STRIDE;
    float* sW2  = sb1 + 128;
    float* sb2  = sW2 + 256;
    for (int t = threadIdx.x; t < 128 * 128; t += 128) {
        int i = t >> 7, k = t & 127;
        sW1T[k * W1T_STRIDE + i] = w1[t];     // w1[i][k]
    }
    for (int t = threadIdx.x; t < 128; t += 128) sb1[t] = b1[t];
    for (int t = threadIdx.x; t < 256; t += 128) sW2[t] = w2[t];
    if (threadIdx.x < 2) sb2[threadIdx.x] = b2[threadIdx.x];
    __syncthreads();

    int v = blockIdx.x * 128 + threadIdx.x;
    if (v >= NVAR) return;

    float hv[128];
    const float4* hp = (const float4*)(hl + (size_t)v * 128);
    #pragma unroll
    for (int j = 0; j < 32; j++) {
        float4 h = hp[j];
        hv[4*j] = h.x; hv[4*j+1] = h.y; hv[4*j+2] = h.z; hv[4*j+3] = h.w;
    }

    float y0 = sb2[0], y1 = sb2[1];
    #pragma unroll 2
    for (int k = 0; k < 128; k++) {
        float t0 = 0.f, t1 = 0.f, t2 = 0.f, t3 = 0.f;
        const float4* wr = (const float4*)(sW1T + k * W1T_STRIDE);
        #pragma unroll
        for (int i4 = 0; i4 < 32; i4++) {
            float4 w = wr[i4];
            t0 += hv[4*i4    ] * w.x;
            t1 += hv[4*i4 + 1] * w.y;
            t2 += hv[4*i4 + 2] * w.z;
            t3 += hv[4*i4 + 3] * w.w;
        }
        float t = (t0 + t1) + (t2 + t3) + sb1[k];
        float s = silu(t);
        y0 += s * sW2[2 * k];
        y1 += s * sW2[2 * k + 1];
    }
    out[2 * v]     = y0;
    out[2 * v + 1] = y1;
}

// ---------------- launcher ----------------
extern "C" void kernel_launch(void* const* d_in, const int* in_sizes, int n_in,
                              void* d_out, int out_size)
{
    const float* x_lit  = (const float*)d_in[0];
    const float* x_cls  = (const float*)d_in[1];
    const int*   e_lit  = (const int*)  d_in[2];
    const int*   e_cls  = (const int*)  d_in[3];
    const float* enc_w1 = (const float*)d_in[4];
    const float* enc_b1 = (const float*)d_in[5];
    const float* enc_w2 = (const float*)d_in[6];
    const float* enc_b2 = (const float*)d_in[7];
    const float* Wc     = (const float*)d_in[8];
    const float* bc     = (const float*)d_in[9];
    const float* Wl     = (const float*)d_in[10];
    const float* bl     = (const float*)d_in[11];
    const float* out_w1 = (const float*)d_in[12];
    const float* out_b1 = (const float*)d_in[13];
    const float* out_w2 = (const float*)d_in[14];
    const float* out_b2 = (const float*)d_in[15];
    float* y = (float*)d_out;

    float *p_hlA, *p_hlB, *p_hc, *p_m, *p_invl, *p_invc;
    int *p_cl, *p_cc;
    cudaGetSymbolAddress((void**)&p_hlA, g_hlA);
    cudaGetSymbolAddress((void**)&p_hlB, g_hlB);
    cudaGetSymbolAddress((void**)&p_hc,  g_hc);
    cudaGetSymbolAddress((void**)&p_m,   g_m);
    cudaGetSymbolAddress((void**)&p_cl,  g_cnt_lit);
    cudaGetSymbolAddress((void**)&p_cc,  g_cnt_cls);
    cudaGetSymbolAddress((void**)&p_invl, g_inv_lit);
    cudaGetSymbolAddress((void**)&p_invc, g_inv_cls);

    cudaFuncSetAttribute(lit_update,     cudaFuncAttributeMaxDynamicSharedMemorySize, (3 * CH * CH + CH) * 4);
    cudaFuncSetAttribute(readout_kernel, cudaFuncAttributeMaxDynamicSharedMemorySize, (128 * W1T_STRIDE + 128 + 256 + 8) * 4);

    const int TB = 256;

    // 1) degree counts + reciprocals
    zero_f4<<<(N_LIT / 4 + TB - 1) / TB, TB>>>((float4*)p_cl, N_LIT / 4);
    zero_f4<<<(N_CLS / 4 + TB - 1) / TB, TB>>>((float4*)p_cc, N_CLS / 4);
    count_kernel<<<(NE + TB - 1) / TB, TB>>>(e_lit, e_cls, p_cl, p_cc);
    inv_kernel<<<(N_LIT + TB - 1) / TB, TB>>>(p_cl, p_invl, N_LIT);
    inv_kernel<<<(N_CLS + TB - 1) / TB, TB>>>(p_cc, p_invc, N_CLS);

    // 2) encoder
    encoder_kernel<<<(N_LIT + N_CLS + 127) / 128, 128>>>(
        x_lit, x_cls, enc_w1, enc_b1, enc_w2, enc_b2, p_hlA, p_hc);

    // 3) message-passing layers (ping-pong hl)
    float* cur = p_hlA;
    float* nxt = p_hlB;
    const int scatter_blocks = (NE * 16 + TB - 1) / TB;
    for (int l = 0; l < NLAY; l++) {
        // lit -> cls
        zero_f4<<<(N_CLS * 16 + TB - 1) / TB, TB>>>((float4*)p_m, N_CLS * 16);
        scatter_kernel<<<scatter_blocks, TB>>>(cur, e_lit, e_cls, p_m);
        cls_update<<<(N_CLS + 127) / 128, 128>>>(p_hc, p_m, p_invc,
                                                 Wc + (size_t)l * 2 * CH * CH, bc + l * CH);
        // cls -> lit
        zero_f4<<<(N_LIT * 16 + TB - 1) / TB, TB>>>((float4*)p_m, N_LIT * 16);
        scatter_kernel<<<scatter_blocks, TB>>>(p_hc, e_cls, e_lit, p_m);
        lit_update<<<(N_LIT + 127) / 128, 128, (3 * CH * CH + CH) * 4>>>(
            cur, nxt, p_m, p_invl, Wl + (size_t)l * 3 * CH * CH, bl + l * CH);
        float* tmp = cur; cur = nxt; nxt = tmp;
    }

    // 4) readout (after even number of layers, result is back in hlA == cur)
    readout_kernel<<<(NVAR + 127) / 128, 128, (128 * W1T_STRIDE + 128 + 256 + 8) * 4>>>(
        cur, out_w1, out_b1, out_w2, out_b2, y);
}

// round 2
// speedup vs baseline: 1.0634x; 1.0634x over previous
#include <cuda_runtime.h>
#include <cuda_bf16.h>
#include <cstddef>
#include <cstdint>

#define N_LIT 200000
#define N_CLS 800000
#define NE    2400000
#define CH    64
#define NVAR  (N_LIT/2)
#define NLAY  4

typedef unsigned long long u64;

// ---------------- device scratch (static, no allocation) ----------------
__device__ float g_hlA[(size_t)N_LIT * CH];
__device__ float g_hlB[(size_t)N_LIT * CH];
__device__ float g_hc [(size_t)N_CLS * CH];
__device__ float g_m  [(size_t)N_CLS * CH];
__device__ int   g_cnt_lit[N_LIT];
__device__ int   g_cnt_cls[N_CLS];
__device__ float g_inv_lit[N_LIT];
__device__ float g_inv_cls[N_CLS];
__device__ int   g_rs_lit[N_LIT];
__device__ int   g_rs_cls[N_CLS];
__device__ int   g_cur_lit[N_LIT];
__device__ int   g_cur_cls[N_CLS];
__device__ int   g_adj_lit[NE];   // clause indices grouped by literal
__device__ int   g_adj_cls[NE];   // literal indices grouped by clause
__device__ int   g_bsum[1024];

__device__ __forceinline__ float silu(float x) { return x / (1.0f + __expf(-x)); }

// ---- f32x2 packed helpers (FFMA2 path, sm_100+) ----
__device__ __forceinline__ u64 pack2(float lo, float hi) {
    u64 r; asm("mov.b64 %0, {%1,%2};" : "=l"(r) : "f"(lo), "f"(hi)); return r;
}
__device__ __forceinline__ u64 pack_dup(float x) {
    u64 r; asm("mov.b64 %0, {%1,%1};" : "=l"(r) : "f"(x)); return r;
}
__device__ __forceinline__ void fma2(u64& acc, u64 a, u64 b) {
    asm("fma.rn.f32x2 %0, %1, %2, %0;" : "+l"(acc) : "l"(a), "l"(b));
}
__device__ __forceinline__ float2 unpack2(u64 v) {
    float2 f; asm("mov.b64 {%0,%1}, %2;" : "=f"(f.x), "=f"(f.y) : "l"(v)); return f;
}
__device__ __forceinline__ void lds_v2u64(u64& a, u64& b, uint32_t addr) {
    asm("ld.shared.v2.b64 {%0,%1}, [%2];" : "=l"(a), "=l"(b) : "r"(addr));
}

// GEMM block: acc2[32] (64 channels packed) += (x_row * scale) @ W_block
// x_row is a gmem row of CH floats; W block base given as 32-bit smem byte address.
__device__ __forceinline__ void gemm_g(u64* acc2, const float* __restrict__ x,
                                       float scale, uint32_t sw)
{
    #pragma unroll 8
    for (int k = 0; k < CH; k++) {
        u64 xk2 = pack_dup(__ldg(x + k) * scale);
        uint32_t ra = sw + (k << 8);      // k * 64 floats * 4B
        #pragma unroll
        for (int j = 0; j < 16; j++) {
            u64 w0, w1;
            lds_v2u64(w0, w1, ra + (j << 4));
            fma2(acc2[2 * j],     xk2, w0);
            fma2(acc2[2 * j + 1], xk2, w1);
        }
    }
}

// ---------------- prep kernels ----------------
__global__ void count_kernel(const int* __restrict__ el, const int* __restrict__ ec,
                             int* __restrict__ cl, int* __restrict__ cc) {
    int e = blockIdx.x * blockDim.x + threadIdx.x;
    if (e < NE) {
        atomicAdd(cl + el[e], 1);
        atomicAdd(cc + ec[e], 1);
    }
}

__global__ void inv_kernel(const int* __restrict__ cnt, float* __restrict__ inv, int n) {
    int i = blockIdx.x * blockDim.x + threadIdx.x;
    if (i < n) {
        int c = cnt[i];
        inv[i] = (c > 0) ? (1.0f / (float)c) : 1.0f;
    }
}

#define SCAN_B 1024
__global__ void scan_block(const int* __restrict__ cnt, int* __restrict__ out,
                           int* __restrict__ bsum, int n) {
    __shared__ int s[SCAN_B];
    int i = blockIdx.x * SCAN_B + threadIdx.x;
    int v = (i < n) ? cnt[i] : 0;
    s[threadIdx.x] = v; __syncthreads();
    for (int off = 1; off < SCAN_B; off <<= 1) {
        int t = (threadIdx.x >= off) ? s[threadIdx.x - off] : 0;
        __syncthreads();
        s[threadIdx.x] += t;
        __syncthreads();
    }
    if (i < n) out[i] = s[threadIdx.x] - v;   // exclusive within block
    if (threadIdx.x == SCAN_B - 1) bsum[blockIdx.x] = s[SCAN_B - 1];
}

__global__ void scan_sums(int* __restrict__ bsum, int nb) {
    __shared__ int s[SCAN_B];
    int v = (threadIdx.x < nb) ? bsum[threadIdx.x] : 0;
    s[threadIdx.x] = v; __syncthreads();
    for (int off = 1; off < SCAN_B; off <<= 1) {
        int t = (threadIdx.x >= off) ? s[threadIdx.x - off] : 0;
        __syncthreads();
        s[threadIdx.x] += t;
        __syncthreads();
    }
    if (threadIdx.x < nb) bsum[threadIdx.x] = s[threadIdx.x] - v;  // exclusive
}

__global__ void scan_add(int* __restrict__ out, const int* __restrict__ bsum, int n) {
    int i = blockIdx.x * SCAN_B + threadIdx.x;
    if (i < n) out[i] += bsum[blockIdx.x];
}

__global__ void fill_kernel(const int* __restrict__ el, const int* __restrict__ ec,
                            int* __restrict__ curl, int* __restrict__ curc,
                            int* __restrict__ adj_lit, int* __restrict__ adj_cls) {
    int e = blockIdx.x * blockDim.x + threadIdx.x;
    if (e < NE) {
        int l = el[e], c = ec[e];
        adj_cls[atomicAdd(curc + c, 1)] = l;
        adj_lit[atomicAdd(curl + l, 1)] = c;
    }
}

// ---------------- aggregation: warp-per-node coalesced gather ----------------
__global__ void __launch_bounds__(256) agg_kernel(
    const float* __restrict__ src, const int* __restrict__ rs,
    const int* __restrict__ cnt, const int* __restrict__ adj,
    const float* __restrict__ inv, float* __restrict__ m, int n)
{
    int w = (blockIdx.x * 256 + threadIdx.x) >> 5;
    if (w >= n) return;
    int lane = threadIdx.x & 31;
    int start = rs[w], deg = cnt[w];
    float ax = 0.f, ay = 0.f;
    const float2* base = (const float2*)src;
    for (int p = 0; p < deg; p++) {
        int j = __ldg(adj + start + p);
        float2 v = __ldg(base + (size_t)j * 32 + lane);
        ax += v.x; ay += v.y;
    }
    float iv = inv[w];
    float2 o; o.x = ax * iv; o.y = ay * iv;
    ((float2*)m)[(size_t)w * 32 + lane] = o;
}

// ---------------- encoder: h = silu(x@W1+b1)@W2+b2, F=4 ----------------
__global__ void __launch_bounds__(128) encoder_kernel(
    const float* __restrict__ xl, const float* __restrict__ xc,
    const float* __restrict__ w1, const float* __restrict__ b1,
    const float* __restrict__ w2, const float* __restrict__ b2,
    float* __restrict__ hl, float* __restrict__ hc)
{
    __shared__ __align__(16) float sW1[4 * CH];
    __shared__ __align__(16) float sb1[CH];
    __shared__ __align__(16) float sW2[CH * CH];
    __shared__ __align__(16) float sb2[CH];
    for (int t = threadIdx.x; t < 64; t += 128) ((float4*)sW1)[t] = ((const float4*)w1)[t];
    for (int t = threadIdx.x; t < CH * 16; t += 128) ((float4*)sW2)[t] = ((const float4*)w2)[t];
    if (threadIdx.x < CH) { sb1[threadIdx.x] = b1[threadIdx.x]; sb2[threadIdx.x] = b2[threadIdx.x]; }
    __syncthreads();
    uint32_t sw2a = (uint32_t)__cvta_generic_to_shared(sW2);

    int i = blockIdx.x * 128 + threadIdx.x;
    if (i >= N_LIT + N_CLS) return;
    const float* x;
    float* out;
    if (i < N_LIT) { x = xl + (size_t)i * 4;           out = hl + (size_t)i * CH; }
    else           { x = xc + (size_t)(i - N_LIT) * 4; out = hc + (size_t)(i - N_LIT) * CH; }
    float x0 = x[0], x1 = x[1], x2 = x[2], x3 = x[3];

    u64 acc2[32];
    #pragma unroll
    for (int j = 0; j < 16; j++) {
        float4 bv = ((const float4*)sb2)[j];
        acc2[2 * j]     = pack2(bv.x, bv.y);
        acc2[2 * j + 1] = pack2(bv.z, bv.w);
    }

    #pragma unroll 8
    for (int k = 0; k < CH; k++) {
        float t = sb1[k] + x0 * sW1[k] + x1 * sW1[CH + k] + x2 * sW1[2 * CH + k] + x3 * sW1[3 * CH + k];
        u64 s2 = pack_dup(silu(t));
        uint32_t ra = sw2a + (k << 8);
        #pragma unroll
        for (int j = 0; j < 16; j++) {
            u64 w0, w1v;
            lds_v2u64(w0, w1v, ra + (j << 4));
            fma2(acc2[2 * j],     s2, w0);
            fma2(acc2[2 * j + 1], s2, w1v);
        }
    }
    #pragma unroll
    for (int j = 0; j < 16; j++) {
        float2 a = unpack2(acc2[2 * j]);
        float2 b = unpack2(acc2[2 * j + 1]);
        ((float4*)out)[j] = make_float4(a.x, a.y, b.x, b.y);
    }
}

// ---------------- cls update: hc = silu([hc, m] @ Wc + bc), m pre-scaled ----------------
__global__ void __launch_bounds__(128) cls_update(
    float* __restrict__ hc, const float* __restrict__ m,
    const float* __restrict__ W, const float* __restrict__ b)
{
    __shared__ __align__(16) float sW[2 * CH * CH];
    __shared__ __align__(16) float sb[CH];
    for (int t = threadIdx.x; t < 2 * CH * 16; t += 128) ((float4*)sW)[t] = ((const float4*)W)[t];
    if (threadIdx.x < CH) sb[threadIdx.x] = b[threadIdx.x];
    __syncthreads();
    uint32_t swa = (uint32_t)__cvta_generic_to_shared(sW);

    size_t i = (size_t)blockIdx.x * 128 + threadIdx.x;
    if (i >= N_CLS) return;

    u64 acc2[32];
    #pragma unroll
    for (int j = 0; j < 16; j++) {
        float4 bv = ((const float4*)sb)[j];
        acc2[2 * j]     = pack2(bv.x, bv.y);
        acc2[2 * j + 1] = pack2(bv.z, bv.w);
    }

    gemm_g(acc2, hc + i * CH, 1.0f, swa);
    gemm_g(acc2, m  + i * CH, 1.0f, swa + CH * CH * 4);

    float* row = hc + i * CH;
    #pragma unroll
    for (int j = 0; j < 16; j++) {
        float2 a = unpack2(acc2[2 * j]);
        float2 c = unpack2(acc2[2 * j + 1]);
        ((float4*)row)[j] = make_float4(silu(a.x), silu(a.y), silu(c.x), silu(c.y));
    }
}

// ---------------- lit update: hdst = silu([hsrc, m, hsrc_flip] @ Wl + bl) ----------------
__global__ void __launch_bounds__(128) lit_update(
    const float* __restrict__ hsrc, float* __restrict__ hdst,
    const float* __restrict__ m,
    const float* __restrict__ W, const float* __restrict__ b)
{
    extern __shared__ __align__(16) float smem[];
    float* sW = smem;                    // 192*64 floats = 48KB
    float* sb = smem + 3 * CH * CH;
    for (int t = threadIdx.x; t < 3 * CH * 16; t += 128) ((float4*)sW)[t] = ((const float4*)W)[t];
    if (threadIdx.x < CH) sb[threadIdx.x] = b[threadIdx.x];
    __syncthreads();
    uint32_t swa = (uint32_t)__cvta_generic_to_shared(sW);

    size_t i = (size_t)blockIdx.x * 128 + threadIdx.x;
    if (i >= N_LIT) return;

    u64 acc2[32];
    #pragma unroll
    for (int j = 0; j < 16; j++) {
        float4 bv = ((const float4*)sb)[j];
        acc2[2 * j]     = pack2(bv.x, bv.y);
        acc2[2 * j + 1] = pack2(bv.z, bv.w);
    }

    gemm_g(acc2, hsrc + i * CH,        1.0f, swa);
    gemm_g(acc2, m    + i * CH,        1.0f, swa + CH * CH * 4);
    gemm_g(acc2, hsrc + (i ^ 1) * CH,  1.0f, swa + 2 * CH * CH * 4);

    float* out = hdst + i * CH;
    #pragma unroll
    for (int j = 0; j < 16; j++) {
        float2 a = unpack2(acc2[2 * j]);
        float2 c = unpack2(acc2[2 * j + 1]);
        ((float4*)out)[j] = make_float4(silu(a.x), silu(a.y), silu(c.x), silu(c.y));
    }
}

// ---------------- readout ----------------
#define W1T_STRIDE 132   // floats; 528B, 16B-aligned
__global__ void __launch_bounds__(128) readout_kernel(
    const float* __restrict__ hl,
    const float* __restrict__ w1, const float* __restrict__ b1,
    const float* __restrict__ w2, const float* __restrict__ b2,
    float* __restrict__ out)
{
    extern __shared__ __align__(16) float smem[];
    float* sW1T = smem;                       // [128][132] transposed, padded
    float* sb1  = smem + 128 * W1T_STRIDE;
    float* sW2  = sb1 + 128;
    float* sb2  = sW2 + 256;
    for (int t = threadIdx.x; t < 128 * 128; t += 128) {
        int i = t >> 7, k = t & 127;
        sW1T[k * W1T_STRIDE + i] = w1[t];     // w1[i][k]
    }
    sb1[threadIdx.x] = b1[threadIdx.x];
    for (int t = threadIdx.x; t < 256; t += 128) sW2[t] = w2[t];
    if (threadIdx.x < 2) sb2[threadIdx.x] = b2[threadIdx.x];
    __syncthreads();
    uint32_t swa = (uint32_t)__cvta_generic_to_shared(sW1T);

    int v = blockIdx.x * 128 + threadIdx.x;
    if (v >= NVAR) return;

    u64 hv2[64];
    const float4* hp = (const float4*)(hl + (size_t)v * 128);
    #pragma unroll
    for (int j = 0; j < 32; j++) {
        float4 h = __ldg(hp + j);
        hv2[2 * j]     = pack2(h.x, h.y);
        hv2[2 * j + 1] = pack2(h.z, h.w);
    }

    float y0 = sb2[0], y1 = sb2[1];
    #pragma unroll 2
    for (int k = 0; k < 128; k++) {
        u64 t0 = 0, t1 = 0, t2 = 0, t3 = 0;
        uint32_t ra = swa + k * (W1T_STRIDE * 4);
        #pragma unroll
        for (int j = 0; j < 32; j++) {
            u64 w0, w1v;
            lds_v2u64(w0, w1v, ra + (j << 4));
            fma2((j & 1) ? t1 : t0, hv2[2 * j],     w0);
            fma2((j & 1) ? t3 : t2, hv2[2 * j + 1], w1v);
        }
        float2 a = unpack2(t0), bq = unpack2(t1), c = unpack2(t2), d = unpack2(t3);
        float t = ((a.x + a.y) + (bq.x + bq.y)) + ((c.x + c.y) + (d.x + d.y)) + sb1[k];
        float s = silu(t);
        y0 += s * sW2[2 * k];
        y1 += s * sW2[2 * k + 1];
    }
    out[2 * v]     = y0;
    out[2 * v + 1] = y1;
}

// ---------------- launcher ----------------
extern "C" void kernel_launch(void* const* d_in, const int* in_sizes, int n_in,
                              void* d_out, int out_size)
{
    const float* x_lit  = (const float*)d_in[0];
    const float* x_cls  = (const float*)d_in[1];
    const int*   e_lit  = (const int*)  d_in[2];
    const int*   e_cls  = (const int*)  d_in[3];
    const float* enc_w1 = (const float*)d_in[4];
    const float* enc_b1 = (const float*)d_in[5];
    const float* enc_w2 = (const float*)d_in[6];
    const float* enc_b2 = (const float*)d_in[7];
    const float* Wc     = (const float*)d_in[8];
    const float* bc     = (const float*)d_in[9];
    const float* Wl     = (const float*)d_in[10];
    const float* bl     = (const float*)d_in[11];
    const float* out_w1 = (const float*)d_in[12];
    const float* out_b1 = (const float*)d_in[13];
    const float* out_w2 = (const float*)d_in[14];
    const float* out_b2 = (const float*)d_in[15];
    float* y = (float*)d_out;

    float *p_hlA, *p_hlB, *p_hc, *p_m, *p_invl, *p_invc;
    int *p_cl, *p_cc, *p_rsl, *p_rsc, *p_curl, *p_curc, *p_adjl, *p_adjc, *p_bsum;
    cudaGetSymbolAddress((void**)&p_hlA, g_hlA);
    cudaGetSymbolAddress((void**)&p_hlB, g_hlB);
    cudaGetSymbolAddress((void**)&p_hc,  g_hc);
    cudaGetSymbolAddress((void**)&p_m,   g_m);
    cudaGetSymbolAddress((void**)&p_cl,  g_cnt_lit);
    cudaGetSymbolAddress((void**)&p_cc,  g_cnt_cls);
    cudaGetSymbolAddress((void**)&p_invl, g_inv_lit);
    cudaGetSymbolAddress((void**)&p_invc, g_inv_cls);
    cudaGetSymbolAddress((void**)&p_rsl, g_rs_lit);
    cudaGetSymbolAddress((void**)&p_rsc, g_rs_cls);
    cudaGetSymbolAddress((void**)&p_curl, g_cur_lit);
    cudaGetSymbolAddress((void**)&p_curc, g_cur_cls);
    cudaGetSymbolAddress((void**)&p_adjl, g_adj_lit);
    cudaGetSymbolAddress((void**)&p_adjc, g_adj_cls);
    cudaGetSymbolAddress((void**)&p_bsum, g_bsum);

    cudaFuncSetAttribute(lit_update, cudaFuncAttributeMaxDynamicSharedMemorySize,
                         (3 * CH * CH + CH) * 4);
    cudaFuncSetAttribute(readout_kernel, cudaFuncAttributeMaxDynamicSharedMemorySize,
                         (128 * W1T_STRIDE + 128 + 256 + 8) * 4);

    const int TB = 256;

    // 1) degree counts
    cudaMemsetAsync(p_cl, 0, N_LIT * sizeof(int));
    cudaMemsetAsync(p_cc, 0, N_CLS * sizeof(int));
    count_kernel<<<(NE + TB - 1) / TB, TB>>>(e_lit, e_cls, p_cl, p_cc);

    // 2) CSR row starts via scan
    int nb_c = (N_CLS + SCAN_B - 1) / SCAN_B;   // 782
    int nb_l = (N_LIT + SCAN_B - 1) / SCAN_B;   // 196
    scan_block<<<nb_c, SCAN_B>>>(p_cc, p_rsc, p_bsum, N_CLS);
    scan_sums<<<1, SCAN_B>>>(p_bsum, nb_c);
    scan_add<<<nb_c, SCAN_B>>>(p_rsc, p_bsum, N_CLS);
    scan_block<<<nb_l, SCAN_B>>>(p_cl, p_rsl, p_bsum, N_LIT);
    scan_sums<<<1, SCAN_B>>>(p_bsum, nb_l);
    scan_add<<<nb_l, SCAN_B>>>(p_rsl, p_bsum, N_LIT);

    // 3) reciprocals + adjacency fill
    inv_kernel<<<(N_LIT + TB - 1) / TB, TB>>>(p_cl, p_invl, N_LIT);
    inv_kernel<<<(N_CLS + TB - 1) / TB, TB>>>(p_cc, p_invc, N_CLS);
    cudaMemcpyAsync(p_curl, p_rsl, N_LIT * sizeof(int), cudaMemcpyDeviceToDevice);
    cudaMemcpyAsync(p_curc, p_rsc, N_CLS * sizeof(int), cudaMemcpyDeviceToDevice);
    fill_kernel<<<(NE + TB - 1) / TB, TB>>>(e_lit, e_cls, p_curl, p_curc, p_adjl, p_adjc);

    // 4) encoder
    encoder_kernel<<<(N_LIT + N_CLS + 127) / 128, 128>>>(
        x_lit, x_cls, enc_w1, enc_b1, enc_w2, enc_b2, p_hlA, p_hc);

    // 5) message-passing layers
    float* cur = p_hlA;
    float* nxt = p_hlB;
    for (int l = 0; l < NLAY; l++) {
        // lit -> cls
        agg_kernel<<<((size_t)N_CLS * 32 + TB - 1) / TB, TB>>>(
            cur, p_rsc, p_cc, p_adjc, p_invc, p_m, N_CLS);
        cls_update<<<(N_CLS + 127) / 128, 128>>>(
            p_hc, p_m, Wc + (size_t)l * 2 * CH * CH, bc + l * CH);
        // cls -> lit
        agg_kernel<<<((size_t)N_LIT * 32 + TB - 1) / TB, TB>>>(
            p_hc, p_rsl, p_cl, p_adjl, p_invl, p_m, N_LIT);
        lit_update<<<(N_LIT + 127) / 128, 128, (3 * CH * CH + CH) * 4>>>(
            cur, nxt, p_m, Wl + (size_t)l * 3 * CH * CH, bl + l * CH);
        float* tmp = cur; cur = nxt; nxt = tmp;
    }

    // 6) readout
    readout_kernel<<<(NVAR + 127) / 128, 128, (128 * W1T_STRIDE + 128 + 256 + 8) * 4>>>(
        cur, out_w1, out_b1, out_w2, out_b2, y);
}

// round 3
// speedup vs baseline: 1.3881x; 1.3054x over previous
#include <cuda_runtime.h>
#include <cuda_bf16.h>
#include <cstddef>
#include <cstdint>

#define N_LIT 200000
#define N_CLS 800000
#define NE    2400000
#define NT    (N_CLS + N_LIT)
#define CH    64
#define NVAR  (N_LIT/2)
#define NLAY  4
#define SCAN_B 1024

typedef unsigned long long u64;

// ---------------- device scratch (static, no allocation) ----------------
__device__ float g_hlA[(size_t)N_LIT * CH];
__device__ float g_hlB[(size_t)N_LIT * CH];
__device__ float g_hc [(size_t)N_CLS * CH];
__device__ float g_m  [(size_t)N_CLS * CH];
__device__ int   g_cnt[NT];          // zero-initialized; re-zeroed by fill_kernel each call
__device__ float g_inv[NT];
__device__ int   g_rs [NT + 1];
__device__ int   g_cur[NT];
__device__ int   g_adj[2 * NE];      // [0,NE): lits grouped by clause; [NE,2NE): clauses by literal
__device__ int   g_bsum[1024];

__device__ __forceinline__ float silu(float x) { return x / (1.0f + __expf(-x)); }

// ---- f32x2 packed helpers (FFMA2 path, sm_100+) ----
__device__ __forceinline__ u64 pack2(float lo, float hi) {
    u64 r; asm("mov.b64 %0, {%1,%2};" : "=l"(r) : "f"(lo), "f"(hi)); return r;
}
__device__ __forceinline__ u64 pack_dup(float x) {
    u64 r; asm("mov.b64 %0, {%1,%1};" : "=l"(r) : "f"(x)); return r;
}
__device__ __forceinline__ void fma2(u64& acc, u64 a, u64 b) {
    asm("fma.rn.f32x2 %0, %1, %2, %0;" : "+l"(acc) : "l"(a), "l"(b));
}
__device__ __forceinline__ float2 unpack2(u64 v) {
    float2 f; asm("mov.b64 {%0,%1}, %2;" : "=f"(f.x), "=f"(f.y) : "l"(v)); return f;
}
__device__ __forceinline__ void lds_v2u64(u64& a, u64& b, uint32_t addr) {
    asm("ld.shared.v2.b64 {%0,%1}, [%2];" : "=l"(a), "=l"(b) : "r"(addr));
}

// acc2[32] += x_row[0..63] @ W_block (W in smem at byte addr sw, row-major 64 wide)
// x row loaded via LDG.128 (4x fewer L1tex wavefronts than scalar).
__device__ __forceinline__ void gemm_v(u64* acc2, const float* __restrict__ x, uint32_t sw)
{
    #pragma unroll
    for (int kk = 0; kk < 4; kk++) {
        float4 xv0 = __ldg((const float4*)x + kk * 4 + 0);
        float4 xv1 = __ldg((const float4*)x + kk * 4 + 1);
        float4 xv2 = __ldg((const float4*)x + kk * 4 + 2);
        float4 xv3 = __ldg((const float4*)x + kk * 4 + 3);
        float xs[16] = {xv0.x, xv0.y, xv0.z, xv0.w,
                        xv1.x, xv1.y, xv1.z, xv1.w,
                        xv2.x, xv2.y, xv2.z, xv2.w,
                        xv3.x, xv3.y, xv3.z, xv3.w};
        #pragma unroll
        for (int e = 0; e < 16; e++) {
            u64 xk2 = pack_dup(xs[e]);
            uint32_t ra = sw + ((kk * 16 + e) << 8);
            #pragma unroll
            for (int j = 0; j < 16; j++) {
                u64 w0, w1;
                lds_v2u64(w0, w1, ra + (j << 4));
                fma2(acc2[2 * j],     xk2, w0);
                fma2(acc2[2 * j + 1], xk2, w1);
            }
        }
    }
}

// ---------------- 1) encoder + edge counting (fused) ----------------
__global__ void __launch_bounds__(128) encoder_kernel(
    const float* __restrict__ xl, const float* __restrict__ xc,
    const float* __restrict__ w1, const float* __restrict__ b1,
    const float* __restrict__ w2, const float* __restrict__ b2,
    const int* __restrict__ el, const int* __restrict__ ec,
    int* __restrict__ cnt,
    float* __restrict__ hl, float* __restrict__ hc)
{
    __shared__ __align__(16) float sW1[4 * CH];
    __shared__ __align__(16) float sb1[CH];
    __shared__ __align__(16) float sW2[CH * CH];
    __shared__ __align__(16) float sb2[CH];
    for (int t = threadIdx.x; t < 64; t += 128) ((float4*)sW1)[t] = ((const float4*)w1)[t];
    for (int t = threadIdx.x; t < CH * 16; t += 128) ((float4*)sW2)[t] = ((const float4*)w2)[t];
    if (threadIdx.x < CH) { sb1[threadIdx.x] = b1[threadIdx.x]; sb2[threadIdx.x] = b2[threadIdx.x]; }
    __syncthreads();
    uint32_t sw2a = (uint32_t)__cvta_generic_to_shared(sW2);

    int i = blockIdx.x * 128 + threadIdx.x;
    int stride = gridDim.x * 128;

    // fused edge degree counting (cnt was zeroed by previous call / static init)
    for (size_t e = i; e < NE; e += stride) {
        atomicAdd(cnt + __ldg(ec + e), 1);
        atomicAdd(cnt + N_CLS + __ldg(el + e), 1);
    }

    if (i >= NT) return;
    const float* x;
    float* out;
    if (i < N_LIT) { x = xl + (size_t)i * 4;           out = hl + (size_t)i * CH; }
    else           { x = xc + (size_t)(i - N_LIT) * 4; out = hc + (size_t)(i - N_LIT) * CH; }
    float4 xv = __ldg((const float4*)x);

    u64 acc2[32];
    #pragma unroll
    for (int j = 0; j < 16; j++) {
        float4 bv = ((const float4*)sb2)[j];
        acc2[2 * j]     = pack2(bv.x, bv.y);
        acc2[2 * j + 1] = pack2(bv.z, bv.w);
    }

    #pragma unroll 8
    for (int k = 0; k < CH; k++) {
        float t = sb1[k] + xv.x * sW1[k] + xv.y * sW1[CH + k] + xv.z * sW1[2 * CH + k] + xv.w * sW1[3 * CH + k];
        u64 s2 = pack_dup(silu(t));
        uint32_t ra = sw2a + (k << 8);
        #pragma unroll
        for (int j = 0; j < 16; j++) {
            u64 w0, w1v;
            lds_v2u64(w0, w1v, ra + (j << 4));
            fma2(acc2[2 * j],     s2, w0);
            fma2(acc2[2 * j + 1], s2, w1v);
        }
    }
    #pragma unroll
    for (int j = 0; j < 16; j++) {
        float2 a = unpack2(acc2[2 * j]);
        float2 b = unpack2(acc2[2 * j + 1]);
        ((float4*)out)[j] = make_float4(a.x, a.y, b.x, b.y);
    }
}

// ---------------- 2-4) concatenated scan over cnt[NT] ----------------
__global__ void reduce_block(const int* __restrict__ cnt, int* __restrict__ bsum, int n) {
    __shared__ int s[SCAN_B];
    int i = blockIdx.x * SCAN_B + threadIdx.x;
    s[threadIdx.x] = (i < n) ? cnt[i] : 0;
    __syncthreads();
    for (int off = 512; off > 0; off >>= 1) {
        if (threadIdx.x < off) s[threadIdx.x] += s[threadIdx.x + off];
        __syncthreads();
    }
    if (threadIdx.x == 0) bsum[blockIdx.x] = s[0];
}

__global__ void scan_sums(int* __restrict__ bsum, int nb) {
    __shared__ int s[SCAN_B];
    int v = (threadIdx.x < nb) ? bsum[threadIdx.x] : 0;
    s[threadIdx.x] = v; __syncthreads();
    for (int off = 1; off < SCAN_B; off <<= 1) {
        int t = (threadIdx.x >= off) ? s[threadIdx.x - off] : 0;
        __syncthreads();
        s[threadIdx.x] += t;
        __syncthreads();
    }
    if (threadIdx.x < nb) bsum[threadIdx.x] = s[threadIdx.x] - v;  // exclusive
}

__global__ void scan_apply(const int* __restrict__ cnt, const int* __restrict__ bsum,
                           int* __restrict__ rs, int* __restrict__ cur,
                           float* __restrict__ inv, int n) {
    __shared__ int s[SCAN_B];
    int i = blockIdx.x * SCAN_B + threadIdx.x;
    int v = (i < n) ? cnt[i] : 0;
    s[threadIdx.x] = v; __syncthreads();
    for (int off = 1; off < SCAN_B; off <<= 1) {
        int t = (threadIdx.x >= off) ? s[threadIdx.x - off] : 0;
        __syncthreads();
        s[threadIdx.x] += t;
        __syncthreads();
    }
    if (i < n) {
        int r = s[threadIdx.x] - v + bsum[blockIdx.x];
        rs[i] = r;
        cur[i] = r;
        inv[i] = (v > 0) ? (1.0f / (float)v) : 1.0f;
    }
    if (i == 0) rs[n] = 2 * NE;
}

// ---------------- 5) adjacency fill (+ re-zero cnt for next call) ----------------
__global__ void fill_kernel(const int* __restrict__ el, const int* __restrict__ ec,
                            int* __restrict__ cur, int* __restrict__ adj,
                            int* __restrict__ cnt) {
    int e = blockIdx.x * 256 + threadIdx.x;
    if (e < NT) cnt[e] = 0;   // counts fully consumed by scan_apply; reset for next call
    if (e < NE) {
        int l = __ldg(el + e), c = __ldg(ec + e);
        adj[atomicAdd(cur + c, 1)]         = l;
        adj[atomicAdd(cur + N_CLS + l, 1)] = c;
    }
}

// ---------------- aggregation: warp-per-node gather, MLP=4 ----------------
__global__ void __launch_bounds__(256) agg_kernel(
    const float* __restrict__ src, const int* __restrict__ rs,
    const int* __restrict__ adj, const float* __restrict__ inv,
    float* __restrict__ m, int n)
{
    int w = (blockIdx.x * 256 + threadIdx.x) >> 5;
    if (w >= n) return;
    int lane = threadIdx.x & 31;
    int start = __ldg(rs + w), end = __ldg(rs + w + 1);
    const float2* base = (const float2*)src;
    float ax = 0.f, ay = 0.f;
    int p = start;
    for (; p + 4 <= end; p += 4) {
        int j0 = __ldg(adj + p),     j1 = __ldg(adj + p + 1);
        int j2 = __ldg(adj + p + 2), j3 = __ldg(adj + p + 3);
        float2 v0 = __ldg(base + (size_t)j0 * 32 + lane);
        float2 v1 = __ldg(base + (size_t)j1 * 32 + lane);
        float2 v2 = __ldg(base + (size_t)j2 * 32 + lane);
        float2 v3 = __ldg(base + (size_t)j3 * 32 + lane);
        ax += (v0.x + v1.x) + (v2.x + v3.x);
        ay += (v0.y + v1.y) + (v2.y + v3.y);
    }
    for (; p < end; p++) {
        int j = __ldg(adj + p);
        float2 v = __ldg(base + (size_t)j * 32 + lane);
        ax += v.x; ay += v.y;
    }
    float iv = inv[w];
    ((float2*)m)[(size_t)w * 32 + lane] = make_float2(ax * iv, ay * iv);
}

// ---------------- cls update: hc = silu([hc, m] @ Wc + bc) in place ----------------
__global__ void __launch_bounds__(128) cls_update(
    float* __restrict__ hc, const float* __restrict__ m,
    const float* __restrict__ W, const float* __restrict__ b)
{
    __shared__ __align__(16) float sW[2 * CH * CH];
    __shared__ __align__(16) float sb[CH];
    for (int t = threadIdx.x; t < 2 * CH * 16; t += 128) ((float4*)sW)[t] = ((const float4*)W)[t];
    if (threadIdx.x < CH) sb[threadIdx.x] = b[threadIdx.x];
    __syncthreads();
    uint32_t swa = (uint32_t)__cvta_generic_to_shared(sW);

    size_t i = (size_t)blockIdx.x * 128 + threadIdx.x;
    if (i >= N_CLS) return;

    u64 acc2[32];
    #pragma unroll
    for (int j = 0; j < 16; j++) {
        float4 bv = ((const float4*)sb)[j];
        acc2[2 * j]     = pack2(bv.x, bv.y);
        acc2[2 * j + 1] = pack2(bv.z, bv.w);
    }

    gemm_v(acc2, hc + i * CH, swa);
    gemm_v(acc2, m  + i * CH, swa + CH * CH * 4);

    float* row = hc + i * CH;
    #pragma unroll
    for (int j = 0; j < 16; j++) {
        float2 a = unpack2(acc2[2 * j]);
        float2 c = unpack2(acc2[2 * j + 1]);
        ((float4*)row)[j] = make_float4(silu(a.x), silu(a.y), silu(c.x), silu(c.y));
    }
}

// ---------------- lit update: hdst = silu([hsrc, m, hsrc_flip] @ Wl + bl) ----------------
__global__ void __launch_bounds__(128) lit_update(
    const float* __restrict__ hsrc, float* __restrict__ hdst,
    const float* __restrict__ m,
    const float* __restrict__ W, const float* __restrict__ b)
{
    extern __shared__ __align__(16) float smem[];
    float* sW = smem;                    // 192*64 floats = 48KB
    float* sb = smem + 3 * CH * CH;
    for (int t = threadIdx.x; t < 3 * CH * 16; t += 128) ((float4*)sW)[t] = ((const float4*)W)[t];
    if (threadIdx.x < CH) sb[threadIdx.x] = b[threadIdx.x];
    __syncthreads();
    uint32_t swa = (uint32_t)__cvta_generic_to_shared(sW);

    size_t i = (size_t)blockIdx.x * 128 + threadIdx.x;
    if (i >= N_LIT) return;

    u64 acc2[32];
    #pragma unroll
    for (int j = 0; j < 16; j++) {
        float4 bv = ((const float4*)sb)[j];
        acc2[2 * j]     = pack2(bv.x, bv.y);
        acc2[2 * j + 1] = pack2(bv.z, bv.w);
    }

    gemm_v(acc2, hsrc + i * CH,       swa);
    gemm_v(acc2, m    + i * CH,       swa + CH * CH * 4);
    gemm_v(acc2, hsrc + (i ^ 1) * CH, swa + 2 * CH * CH * 4);

    float* out = hdst + i * CH;
    #pragma unroll
    for (int j = 0; j < 16; j++) {
        float2 a = unpack2(acc2[2 * j]);
        float2 c = unpack2(acc2[2 * j + 1]);
        ((float4*)out)[j] = make_float4(silu(a.x), silu(a.y), silu(c.x), silu(c.y));
    }
}

// ---------------- readout ----------------
#define W1T_STRIDE 132   // floats; 528B, 16B-aligned
__global__ void __launch_bounds__(128) readout_kernel(
    const float* __restrict__ hl,
    const float* __restrict__ w1, const float* __restrict__ b1,
    const float* __restrict__ w2, const float* __restrict__ b2,
    float* __restrict__ out)
{
    extern __shared__ __align__(16) float smem[];
    float* sW1T = smem;                       // [128][132] transposed, padded
    float* sb1  = smem + 128 * W1T_STRIDE;
    float* sW2  = sb1 + 128;
    float* sb2  = sW2 + 256;
    for (int t = threadIdx.x; t < 128 * 128; t += 128) {
        int i = t >> 7, k = t & 127;
        sW1T[k * W1T_STRIDE + i] = w1[t];     // w1[i][k]
    }
    sb1[threadIdx.x] = b1[threadIdx.x];
    for (int t = threadIdx.x; t < 256; t += 128) sW2[t] = w2[t];
    if (threadIdx.x < 2) sb2[threadIdx.x] = b2[threadIdx.x];
    __syncthreads();
    uint32_t swa = (uint32_t)__cvta_generic_to_shared(sW1T);

    int v = blockIdx.x * 128 + threadIdx.x;
    if (v >= NVAR) return;

    u64 hv2[64];
    const float4* hp = (const float4*)(hl + (size_t)v * 128);
    #pragma unroll
    for (int j = 0; j < 32; j++) {
        float4 h = __ldg(hp + j);
        hv2[2 * j]     = pack2(h.x, h.y);
        hv2[2 * j + 1] = pack2(h.z, h.w);
    }

    float y0 = sb2[0], y1 = sb2[1];
    #pragma unroll 2
    for (int k = 0; k < 128; k++) {
        u64 t0 = 0, t1 = 0, t2 = 0, t3 = 0;
        uint32_t ra = swa + k * (W1T_STRIDE * 4);
        #pragma unroll
        for (int j = 0; j < 32; j++) {
            u64 w0, w1v;
            lds_v2u64(w0, w1v, ra + (j << 4));
            fma2((j & 1) ? t1 : t0, hv2[2 * j],     w0);
            fma2((j & 1) ? t3 : t2, hv2[2 * j + 1], w1v);
        }
        float2 a = unpack2(t0), bq = unpack2(t1), c = unpack2(t2), d = unpack2(t3);
        float t = ((a.x + a.y) + (bq.x + bq.y)) + ((c.x + c.y) + (d.x + d.y)) + sb1[k];
        float s = silu(t);
        y0 += s * sW2[2 * k];
        y1 += s * sW2[2 * k + 1];
    }
    out[2 * v]     = y0;
    out[2 * v + 1] = y1;
}

// ---------------- launcher ----------------
extern "C" void kernel_launch(void* const* d_in, const int* in_sizes, int n_in,
                              void* d_out, int out_size)
{
    const float* x_lit  = (const float*)d_in[0];
    const float* x_cls  = (const float*)d_in[1];
    const int*   e_lit  = (const int*)  d_in[2];
    const int*   e_cls  = (const int*)  d_in[3];
    const float* enc_w1 = (const float*)d_in[4];
    const float* enc_b1 = (const float*)d_in[5];
    const float* enc_w2 = (const float*)d_in[6];
    const float* enc_b2 = (const float*)d_in[7];
    const float* Wc     = (const float*)d_in[8];
    const float* bc     = (const float*)d_in[9];
    const float* Wl     = (const float*)d_in[10];
    const float* bl     = (const float*)d_in[11];
    const float* out_w1 = (const float*)d_in[12];
    const float* out_b1 = (const float*)d_in[13];
    const float* out_w2 = (const float*)d_in[14];
    const float* out_b2 = (const float*)d_in[15];
    float* y = (float*)d_out;

    float *p_hlA, *p_hlB, *p_hc, *p_m, *p_inv;
    int *p_cnt, *p_rs, *p_cur, *p_adj, *p_bsum;
    cudaGetSymbolAddress((void**)&p_hlA, g_hlA);
    cudaGetSymbolAddress((void**)&p_hlB, g_hlB);
    cudaGetSymbolAddress((void**)&p_hc,  g_hc);
    cudaGetSymbolAddress((void**)&p_m,   g_m);
    cudaGetSymbolAddress((void**)&p_cnt, g_cnt);
    cudaGetSymbolAddress((void**)&p_inv, g_inv);
    cudaGetSymbolAddress((void**)&p_rs,  g_rs);
    cudaGetSymbolAddress((void**)&p_cur, g_cur);
    cudaGetSymbolAddress((void**)&p_adj, g_adj);
    cudaGetSymbolAddress((void**)&p_bsum, g_bsum);

    cudaFuncSetAttribute(lit_update, cudaFuncAttributeMaxDynamicSharedMemorySize,
                         (3 * CH * CH + CH) * 4);
    cudaFuncSetAttribute(readout_kernel, cudaFuncAttributeMaxDynamicSharedMemorySize,
                         (128 * W1T_STRIDE + 128 + 256 + 8) * 4);

    // 1) encoder + edge counting (cnt zeroed by previous call's fill / static init)
    encoder_kernel<<<(NT + 127) / 128, 128>>>(
        x_lit, x_cls, enc_w1, enc_b1, enc_w2, enc_b2,
        e_lit, e_cls, p_cnt, p_hlA, p_hc);

    // 2-4) scan over concatenated counts -> row starts, cur, inv
    int nb = (NT + SCAN_B - 1) / SCAN_B;   // 977
    reduce_block<<<nb, SCAN_B>>>(p_cnt, p_bsum, NT);
    scan_sums<<<1, SCAN_B>>>(p_bsum, nb);
    scan_apply<<<nb, SCAN_B>>>(p_cnt, p_bsum, p_rs, p_cur, p_inv, NT);

    // 5) adjacency fill + re-zero cnt
    fill_kernel<<<(NE + 255) / 256, 256>>>(e_lit, e_cls, p_cur, p_adj, p_cnt);

    // 6+) message-passing layers
    float* cur = p_hlA;
    float* nxt = p_hlB;
    for (int l = 0; l < NLAY; l++) {
        // lit -> cls
        agg_kernel<<<((size_t)N_CLS * 32 + 255) / 256, 256>>>(
            cur, p_rs, p_adj, p_inv, p_m, N_CLS);
        cls_update<<<(N_CLS + 127) / 128, 128>>>(
            p_hc, p_m, Wc + (size_t)l * 2 * CH * CH, bc + l * CH);
        // cls -> lit
        agg_kernel<<<((size_t)N_LIT * 32 + 255) / 256, 256>>>(
            p_hc, p_rs + N_CLS, p_adj, p_inv + N_CLS, p_m, N_LIT);
        lit_update<<<(N_LIT + 127) / 128, 128, (3 * CH * CH + CH) * 4>>>(
            cur, nxt, p_m, Wl + (size_t)l * 3 * CH * CH, bl + l * CH);
        float* tmp = cur; cur = nxt; nxt = tmp;
    }

    // readout
    readout_kernel<<<(NVAR + 127) / 128, 128, (128 * W1T_STRIDE + 128 + 256 + 8) * 4>>>(
        cur, out_w1, out_b1, out_w2, out_b2, y);
}